// round 7
// baseline (speedup 1.0000x reference)
#include <cuda_runtime.h>
#include <cuda_bf16.h>
#include <stdint.h>

#define USER_NUM 100000
#define ITEM_NUM 100000
#define N_NODES  (USER_NUM + ITEM_NUM)
#define EMB      64
#define N_EDGES  6400000
#define N_LAYERS 3
#define EPS_F    0.1f

// Scratch (__device__ globals: no allocation allowed)
__device__ float g_ego_a[(size_t)N_NODES * EMB];   // 51.2 MB
__device__ float g_ego_b[(size_t)N_NODES * EMB];   // 51.2 MB
__device__ int2  g_perm[(size_t)N_EDGES];          // {col, val_bits} 51.2 MB
__device__ int   g_counts[N_NODES];
__device__ int   g_start[N_NODES];
__device__ int   g_cursor[N_NODES];
__device__ int   g_total;

// ---------------------------------------------------------------------------
// Pass 1: histogram of destination rows (4 edges per thread, int4 reads)
// ---------------------------------------------------------------------------
__global__ void __launch_bounds__(256) hist_kernel(const int* __restrict__ rows)
{
    unsigned e4 = blockIdx.x * 256u + threadIdx.x;
    if (e4 >= N_EDGES / 4) return;
    int4 r = reinterpret_cast<const int4*>(rows)[e4];
    atomicAdd(&g_counts[r.x], 1);
    atomicAdd(&g_counts[r.y], 1);
    atomicAdd(&g_counts[r.z], 1);
    atomicAdd(&g_counts[r.w], 1);
}

// ---------------------------------------------------------------------------
// Pass 2: assign contiguous segment starts (order arbitrary).
// ---------------------------------------------------------------------------
__global__ void __launch_bounds__(256) assign_kernel()
{
    unsigned r = blockIdx.x * 256u + threadIdx.x;
    unsigned lane = threadIdx.x & 31u;

    int c = (r < N_NODES) ? g_counts[r] : 0;

    int incl = c;
    #pragma unroll
    for (int o = 1; o < 32; o <<= 1) {
        int n = __shfl_up_sync(0xffffffffu, incl, o);
        if (lane >= (unsigned)o) incl += n;
    }
    int excl = incl - c;

    int base = 0;
    if (lane == 31) base = atomicAdd(&g_total, incl);
    base = __shfl_sync(0xffffffffu, base, 31);

    if (r < N_NODES) {
        int s = base + excl;
        g_start[r]  = s;
        g_cursor[r] = s;
    }
}

// ---------------------------------------------------------------------------
// Pass 3: scatter {col, val} into per-row contiguous segments (4 edges/thread)
// ---------------------------------------------------------------------------
__global__ void __launch_bounds__(256) scatter_kernel(
    const int* __restrict__ rows,
    const int* __restrict__ cols,
    const float* __restrict__ vals)
{
    unsigned e4 = blockIdx.x * 256u + threadIdx.x;
    if (e4 >= N_EDGES / 4) return;
    int4   r = reinterpret_cast<const int4*>(rows)[e4];
    int4   c = reinterpret_cast<const int4*>(cols)[e4];
    float4 v = reinterpret_cast<const float4*>(vals)[e4];
    int p0 = atomicAdd(&g_cursor[r.x], 1);
    g_perm[p0] = make_int2(c.x, __float_as_int(v.x));
    int p1 = atomicAdd(&g_cursor[r.y], 1);
    g_perm[p1] = make_int2(c.y, __float_as_int(v.y));
    int p2 = atomicAdd(&g_cursor[r.z], 1);
    g_perm[p2] = make_int2(c.z, __float_as_int(v.z));
    int p3 = atomicAdd(&g_cursor[r.w], 1);
    g_perm[p3] = make_int2(c.w, __float_as_int(v.w));
}

// ---------------------------------------------------------------------------
// Fused CSR-gather SPMM + perturb + accumulate. fp32 throughout.
// TWO rows per warp: lanes 0-15 row r0, lanes 16-31 row r1; float4/lane.
// 8 independent LDG.128 gathers per batch; __launch_bounds__(256,3) gives
// ptxas register headroom (~84 regs) to actually keep them in flight.
// Edge tiles double-buffered in smem; next tile load overlaps FMA work.
// MODE 0: final = ego ; cl = ego ; store ego
// MODE 1: final += ego ; store ego
// MODE 2: final = (final + ego)/3 ; no ego store
// ---------------------------------------------------------------------------
template <int MODE>
__global__ void __launch_bounds__(256, 3) spmm_perturb_kernel(
    const float* __restrict__ x,
    float* __restrict__ ego_dst,
    const float* __restrict__ noise_k,
    float* __restrict__ final_out,
    float* __restrict__ cl_out)
{
    __shared__ int2 scv[2][8][32];

    const unsigned warp = threadIdx.x >> 5;
    const unsigned lane = threadIdx.x & 31u;
    const unsigned sub  = lane & 15u;         // float4 slot within row
    const unsigned half = lane & 16u;         // 0 = row0, 16 = row1

    unsigned r = blockIdx.x * 16u + warp * 2u + (half >> 4);
    if (r >= N_NODES) return;

    const int s   = g_start[r];
    const int deg = g_counts[r];
    const int degmax = max(deg, __shfl_xor_sync(0xffffffffu, deg, 16));

    float4 acc = make_float4(0.f, 0.f, 0.f, 0.f);

    const float4* __restrict__ x4 = reinterpret_cast<const float4*>(x);

    // prefetch first edge tile (streaming: perm is read once per layer)
    int2 cv_next = ((int)sub < deg) ? __ldcs(&g_perm[s + sub]) : make_int2(0, 0);
    int buf = 0;

    for (int base = 0; base < degmax; base += 16, buf ^= 1) {
        scv[buf][warp][lane] = cv_next;
        __syncwarp();

        // issue next tile's coalesced load early (overlaps with gathers/FMA)
        int nidx = base + 16 + (int)sub;
        cv_next = (nidx < deg) ? __ldcs(&g_perm[s + nidx]) : make_int2(0, 0);

        #pragma unroll
        for (int j0 = 0; j0 < 16; j0 += 8) {
            int2 c[8];
            #pragma unroll
            for (int j = 0; j < 8; j++)
                c[j] = scv[buf][warp][half + j0 + j];

            float4 xx[8];
            #pragma unroll
            for (int j = 0; j < 8; j++)
                xx[j] = __ldg(x4 + (size_t)c[j].x * 16 + sub);

            #pragma unroll
            for (int j = 0; j < 8; j++) {
                float v = __int_as_float(c[j].y);
                acc.x = fmaf(v, xx[j].x, acc.x);
                acc.y = fmaf(v, xx[j].y, acc.y);
                acc.z = fmaf(v, xx[j].z, acc.z);
                acc.w = fmaf(v, xx[j].w, acc.w);
            }
        }
    }

    // Perturb: ego += sign(ego) * (noise / max(||noise||,1e-12)) * EPS
    size_t f4_idx = (size_t)r * 16 + sub;     // float4 index into [N,64]
    float4 nv = __ldcs(reinterpret_cast<const float4*>(noise_k) + f4_idx);
    float ss = nv.x * nv.x + nv.y * nv.y + nv.z * nv.z + nv.w * nv.w;
    #pragma unroll
    for (int o = 8; o > 0; o >>= 1)           // reduce within 16-lane half
        ss += __shfl_xor_sync(0xffffffffu, ss, o);
    float f = EPS_F / fmaxf(sqrtf(ss), 1e-12f);

    float4 e;
    {
        float sx = (acc.x > 0.f) ? 1.f : ((acc.x < 0.f) ? -1.f : 0.f);
        float sy = (acc.y > 0.f) ? 1.f : ((acc.y < 0.f) ? -1.f : 0.f);
        float sz = (acc.z > 0.f) ? 1.f : ((acc.z < 0.f) ? -1.f : 0.f);
        float sw = (acc.w > 0.f) ? 1.f : ((acc.w < 0.f) ? -1.f : 0.f);
        e.x = fmaf(sx * nv.x, f, acc.x);
        e.y = fmaf(sy * nv.y, f, acc.y);
        e.z = fmaf(sz * nv.z, f, acc.z);
        e.w = fmaf(sw * nv.w, f, acc.w);
    }

    if (MODE != 2)
        reinterpret_cast<float4*>(ego_dst)[f4_idx] = e;

    float4* fo = reinterpret_cast<float4*>(final_out) + f4_idx;
    if (MODE == 0) {
        *fo = e;
        reinterpret_cast<float4*>(cl_out)[f4_idx] = e;
    } else if (MODE == 1) {
        float4 a = *fo;
        a.x += e.x; a.y += e.y; a.z += e.z; a.w += e.w;
        *fo = a;
    } else {
        float4 a = *fo;
        const float inv3 = 1.0f / 3.0f;
        a.x = (a.x + e.x) * inv3;
        a.y = (a.y + e.y) * inv3;
        a.z = (a.z + e.z) * inv3;
        a.w = (a.w + e.w) * inv3;
        *fo = a;
    }
}

extern "C" void kernel_launch(void* const* d_in, const int* in_sizes, int n_in,
                              void* d_out, int out_size)
{
    const float* user_emb = (const float*)d_in[0];
    const float* item_emb = (const float*)d_in[1];
    const int*   adj_rows = (const int*)d_in[2];
    const int*   adj_cols = (const int*)d_in[3];
    const float* adj_vals = (const float*)d_in[4];
    const float* noise    = (const float*)d_in[5];

    float* out_final = (float*)d_out;
    float* out_cl    = (float*)d_out + (size_t)N_NODES * EMB;

    float *bufA = nullptr, *bufB = nullptr;
    int *counts_p = nullptr, *total_p = nullptr;
    cudaGetSymbolAddress((void**)&bufA, g_ego_a);
    cudaGetSymbolAddress((void**)&bufB, g_ego_b);
    cudaGetSymbolAddress((void**)&counts_p, g_counts);
    cudaGetSymbolAddress((void**)&total_p, g_total);

    cudaMemsetAsync(counts_p, 0, (size_t)N_NODES * sizeof(int));
    cudaMemsetAsync(total_p, 0, sizeof(int));

    const unsigned edge4_blocks = (N_EDGES / 4 + 255) / 256;
    const unsigned node_blocks  = (N_NODES + 255) / 256;

    hist_kernel<<<edge4_blocks, 256>>>(adj_rows);
    assign_kernel<<<node_blocks, 256>>>();
    scatter_kernel<<<edge4_blocks, 256>>>(adj_rows, adj_cols, adj_vals);

    // ego0 = concat(user_emb, item_emb)
    cudaMemcpyAsync(bufA, user_emb, (size_t)USER_NUM * EMB * sizeof(float),
                    cudaMemcpyDeviceToDevice);
    cudaMemcpyAsync(bufA + (size_t)USER_NUM * EMB, item_emb,
                    (size_t)ITEM_NUM * EMB * sizeof(float),
                    cudaMemcpyDeviceToDevice);

    const unsigned spmm_blocks = (N_NODES + 15) / 16;  // 8 warps, 2 rows/warp

    spmm_perturb_kernel<0><<<spmm_blocks, 256>>>(bufA, bufB,
        noise + (size_t)0 * N_NODES * EMB, out_final, out_cl);
    spmm_perturb_kernel<1><<<spmm_blocks, 256>>>(bufB, bufA,
        noise + (size_t)1 * N_NODES * EMB, out_final, out_cl);
    spmm_perturb_kernel<2><<<spmm_blocks, 256>>>(bufA, bufB,
        noise + (size_t)2 * N_NODES * EMB, out_final, out_cl);
}

// round 8
// speedup vs baseline: 1.1915x; 1.1915x over previous
#include <cuda_runtime.h>
#include <cuda_bf16.h>
#include <stdint.h>

#define USER_NUM 100000
#define ITEM_NUM 100000
#define N_NODES  (USER_NUM + ITEM_NUM)
#define EMB      64
#define N_EDGES  6400000
#define N_LAYERS 3
#define EPS_F    0.1f

// Scratch (__device__ globals: no allocation allowed)
__device__ float g_ego_a[(size_t)N_NODES * EMB];   // 51.2 MB
__device__ float g_ego_b[(size_t)N_NODES * EMB];   // 51.2 MB
__device__ int2  g_perm[(size_t)N_EDGES];          // {col, val_bits} 51.2 MB
__device__ int   g_counts[N_NODES];
__device__ int   g_start[N_NODES];
__device__ int   g_cursor[N_NODES];
__device__ int   g_total;

// ---------------------------------------------------------------------------
// Pass 1: histogram of destination rows (4 edges per thread, int4 reads)
// ---------------------------------------------------------------------------
__global__ void __launch_bounds__(256) hist_kernel(const int* __restrict__ rows)
{
    unsigned e4 = blockIdx.x * 256u + threadIdx.x;
    if (e4 >= N_EDGES / 4) return;
    int4 r = reinterpret_cast<const int4*>(rows)[e4];
    atomicAdd(&g_counts[r.x], 1);
    atomicAdd(&g_counts[r.y], 1);
    atomicAdd(&g_counts[r.z], 1);
    atomicAdd(&g_counts[r.w], 1);
}

// ---------------------------------------------------------------------------
// Pass 2: assign contiguous segment starts (order arbitrary).
// ---------------------------------------------------------------------------
__global__ void __launch_bounds__(256) assign_kernel()
{
    unsigned r = blockIdx.x * 256u + threadIdx.x;
    unsigned lane = threadIdx.x & 31u;

    int c = (r < N_NODES) ? g_counts[r] : 0;

    int incl = c;
    #pragma unroll
    for (int o = 1; o < 32; o <<= 1) {
        int n = __shfl_up_sync(0xffffffffu, incl, o);
        if (lane >= (unsigned)o) incl += n;
    }
    int excl = incl - c;

    int base = 0;
    if (lane == 31) base = atomicAdd(&g_total, incl);
    base = __shfl_sync(0xffffffffu, base, 31);

    if (r < N_NODES) {
        int s = base + excl;
        g_start[r]  = s;
        g_cursor[r] = s;
    }
}

// ---------------------------------------------------------------------------
// Pass 3: scatter {col, val} into per-row contiguous segments (4 edges/thread)
// ---------------------------------------------------------------------------
__global__ void __launch_bounds__(256) scatter_kernel(
    const int* __restrict__ rows,
    const int* __restrict__ cols,
    const float* __restrict__ vals)
{
    unsigned e4 = blockIdx.x * 256u + threadIdx.x;
    if (e4 >= N_EDGES / 4) return;
    int4   r = reinterpret_cast<const int4*>(rows)[e4];
    int4   c = reinterpret_cast<const int4*>(cols)[e4];
    float4 v = reinterpret_cast<const float4*>(vals)[e4];
    int p0 = atomicAdd(&g_cursor[r.x], 1);
    g_perm[p0] = make_int2(c.x, __float_as_int(v.x));
    int p1 = atomicAdd(&g_cursor[r.y], 1);
    g_perm[p1] = make_int2(c.y, __float_as_int(v.y));
    int p2 = atomicAdd(&g_cursor[r.z], 1);
    g_perm[p2] = make_int2(c.z, __float_as_int(v.z));
    int p3 = atomicAdd(&g_cursor[r.w], 1);
    g_perm[p3] = make_int2(c.w, __float_as_int(v.w));
}

// ---------------------------------------------------------------------------
// Fused CSR-gather SPMM + perturb + accumulate. fp32 throughout.
// TWO rows per warp: lanes 0-15 row r0, lanes 16-31 row r1; float4/lane.
// Batch-4 gathers (best occ*MLP point per R4/R7 data); edge tiles
// double-buffered in smem with early prefetch of the next tile.
// Streaming data (perm, noise, cl) uses evict-first hints so the x gather
// buffer stays L2-resident.
// MODE 0: final = ego ; cl = ego ; store ego
// MODE 1: final += ego ; store ego
// MODE 2: final = (final + ego)/3 ; no ego store
// ---------------------------------------------------------------------------
template <int MODE>
__global__ void __launch_bounds__(256) spmm_perturb_kernel(
    const float* __restrict__ x,
    float* __restrict__ ego_dst,
    const float* __restrict__ noise_k,
    float* __restrict__ final_out,
    float* __restrict__ cl_out)
{
    __shared__ int2 scv[2][8][32];

    const unsigned warp = threadIdx.x >> 5;
    const unsigned lane = threadIdx.x & 31u;
    const unsigned sub  = lane & 15u;         // float4 slot within row
    const unsigned half = lane & 16u;         // 0 = row0, 16 = row1

    unsigned r = blockIdx.x * 16u + warp * 2u + (half >> 4);
    if (r >= N_NODES) return;

    const int s   = g_start[r];
    const int deg = g_counts[r];
    const int degmax = max(deg, __shfl_xor_sync(0xffffffffu, deg, 16));

    float4 acc = make_float4(0.f, 0.f, 0.f, 0.f);

    const float4* __restrict__ x4 = reinterpret_cast<const float4*>(x);

    // prefetch first edge tile (evict-first: perm is read once per layer)
    int2 cv_next = ((int)sub < deg) ? __ldcs(&g_perm[s + sub]) : make_int2(0, 0);
    int buf = 0;

    for (int base = 0; base < degmax; base += 16, buf ^= 1) {
        scv[buf][warp][lane] = cv_next;
        __syncwarp();

        // issue next tile's coalesced load early (overlaps with gathers/FMA)
        int nidx = base + 16 + (int)sub;
        cv_next = (nidx < deg) ? __ldcs(&g_perm[s + nidx]) : make_int2(0, 0);

        #pragma unroll
        for (int j0 = 0; j0 < 16; j0 += 4) {
            int2 c0 = scv[buf][warp][half + j0 + 0];
            int2 c1 = scv[buf][warp][half + j0 + 1];
            int2 c2 = scv[buf][warp][half + j0 + 2];
            int2 c3 = scv[buf][warp][half + j0 + 3];
            float4 x0 = __ldg(x4 + (size_t)c0.x * 16 + sub);
            float4 x1 = __ldg(x4 + (size_t)c1.x * 16 + sub);
            float4 x2 = __ldg(x4 + (size_t)c2.x * 16 + sub);
            float4 x3 = __ldg(x4 + (size_t)c3.x * 16 + sub);
            float v0 = __int_as_float(c0.y);
            float v1 = __int_as_float(c1.y);
            float v2 = __int_as_float(c2.y);
            float v3 = __int_as_float(c3.y);
            acc.x = fmaf(v0, x0.x, acc.x); acc.y = fmaf(v0, x0.y, acc.y);
            acc.z = fmaf(v0, x0.z, acc.z); acc.w = fmaf(v0, x0.w, acc.w);
            acc.x = fmaf(v1, x1.x, acc.x); acc.y = fmaf(v1, x1.y, acc.y);
            acc.z = fmaf(v1, x1.z, acc.z); acc.w = fmaf(v1, x1.w, acc.w);
            acc.x = fmaf(v2, x2.x, acc.x); acc.y = fmaf(v2, x2.y, acc.y);
            acc.z = fmaf(v2, x2.z, acc.z); acc.w = fmaf(v2, x2.w, acc.w);
            acc.x = fmaf(v3, x3.x, acc.x); acc.y = fmaf(v3, x3.y, acc.y);
            acc.z = fmaf(v3, x3.z, acc.z); acc.w = fmaf(v3, x3.w, acc.w);
        }
    }

    // Perturb: ego += sign(ego) * (noise / max(||noise||,1e-12)) * EPS
    size_t f4_idx = (size_t)r * 16 + sub;     // float4 index into [N,64]
    float4 nv = __ldcs(reinterpret_cast<const float4*>(noise_k) + f4_idx);
    float ss = nv.x * nv.x + nv.y * nv.y + nv.z * nv.z + nv.w * nv.w;
    #pragma unroll
    for (int o = 8; o > 0; o >>= 1)           // reduce within 16-lane half
        ss += __shfl_xor_sync(0xffffffffu, ss, o);
    float f = EPS_F / fmaxf(sqrtf(ss), 1e-12f);

    float4 e;
    {
        float sx = (acc.x > 0.f) ? 1.f : ((acc.x < 0.f) ? -1.f : 0.f);
        float sy = (acc.y > 0.f) ? 1.f : ((acc.y < 0.f) ? -1.f : 0.f);
        float sz = (acc.z > 0.f) ? 1.f : ((acc.z < 0.f) ? -1.f : 0.f);
        float sw = (acc.w > 0.f) ? 1.f : ((acc.w < 0.f) ? -1.f : 0.f);
        e.x = fmaf(sx * nv.x, f, acc.x);
        e.y = fmaf(sy * nv.y, f, acc.y);
        e.z = fmaf(sz * nv.z, f, acc.z);
        e.w = fmaf(sw * nv.w, f, acc.w);
    }

    if (MODE != 2)
        reinterpret_cast<float4*>(ego_dst)[f4_idx] = e;

    float4* fo = reinterpret_cast<float4*>(final_out) + f4_idx;
    if (MODE == 0) {
        *fo = e;
        __stcs(reinterpret_cast<float4*>(cl_out) + f4_idx, e);  // cl never re-read
    } else if (MODE == 1) {
        float4 a = *fo;
        a.x += e.x; a.y += e.y; a.z += e.z; a.w += e.w;
        *fo = a;
    } else {
        float4 a = *fo;
        const float inv3 = 1.0f / 3.0f;
        a.x = (a.x + e.x) * inv3;
        a.y = (a.y + e.y) * inv3;
        a.z = (a.z + e.z) * inv3;
        a.w = (a.w + e.w) * inv3;
        __stcs(fo, a);  // final last write, never re-read
    }
}

extern "C" void kernel_launch(void* const* d_in, const int* in_sizes, int n_in,
                              void* d_out, int out_size)
{
    const float* user_emb = (const float*)d_in[0];
    const float* item_emb = (const float*)d_in[1];
    const int*   adj_rows = (const int*)d_in[2];
    const int*   adj_cols = (const int*)d_in[3];
    const float* adj_vals = (const float*)d_in[4];
    const float* noise    = (const float*)d_in[5];

    float* out_final = (float*)d_out;
    float* out_cl    = (float*)d_out + (size_t)N_NODES * EMB;

    float *bufA = nullptr, *bufB = nullptr;
    int *counts_p = nullptr, *total_p = nullptr;
    cudaGetSymbolAddress((void**)&bufA, g_ego_a);
    cudaGetSymbolAddress((void**)&bufB, g_ego_b);
    cudaGetSymbolAddress((void**)&counts_p, g_counts);
    cudaGetSymbolAddress((void**)&total_p, g_total);

    cudaMemsetAsync(counts_p, 0, (size_t)N_NODES * sizeof(int));
    cudaMemsetAsync(total_p, 0, sizeof(int));

    const unsigned edge4_blocks = (N_EDGES / 4 + 255) / 256;
    const unsigned node_blocks  = (N_NODES + 255) / 256;

    hist_kernel<<<edge4_blocks, 256>>>(adj_rows);
    assign_kernel<<<node_blocks, 256>>>();
    scatter_kernel<<<edge4_blocks, 256>>>(adj_rows, adj_cols, adj_vals);

    // ego0 = concat(user_emb, item_emb)
    cudaMemcpyAsync(bufA, user_emb, (size_t)USER_NUM * EMB * sizeof(float),
                    cudaMemcpyDeviceToDevice);
    cudaMemcpyAsync(bufA + (size_t)USER_NUM * EMB, item_emb,
                    (size_t)ITEM_NUM * EMB * sizeof(float),
                    cudaMemcpyDeviceToDevice);

    const unsigned spmm_blocks = (N_NODES + 15) / 16;  // 8 warps, 2 rows/warp

    spmm_perturb_kernel<0><<<spmm_blocks, 256>>>(bufA, bufB,
        noise + (size_t)0 * N_NODES * EMB, out_final, out_cl);
    spmm_perturb_kernel<1><<<spmm_blocks, 256>>>(bufB, bufA,
        noise + (size_t)1 * N_NODES * EMB, out_final, out_cl);
    spmm_perturb_kernel<2><<<spmm_blocks, 256>>>(bufA, bufB,
        noise + (size_t)2 * N_NODES * EMB, out_final, out_cl);
}